// round 4
// baseline (speedup 1.0000x reference)
#include <cuda_runtime.h>
#include <math.h>

// Shapes: B=8, T=2048, S=3, H=12, W_SPLIT=6, L=512, N_NOISE=4, R=4
// x: [8,2048,48], latents_table: [36,18,512], eps_i: [8,2048,(2^(i+2))^2]
// out = concat(lats [8,2048,18,512], noise0..3)

#define B 8
#define T 2048
#define CH 48
#define LDIM 512
#define WTOT 18
#define TC 128            // t-chunk for lats kernel
#define NTCH (T / TC)     // 16

__device__ float g_mean[B][CH];
__device__ float g_w[B][4][9];

// ---------------- stats: per-batch channel means + gaussian weights ----------
__global__ void stats_kernel(const float* __restrict__ x) {
    __shared__ float sm[CH * 8];
    __shared__ float mean_s[CH];
    int b = blockIdx.x;
    int tid = threadIdx.x;             // 384 threads
    int c = tid % CH, r = tid / CH;    // r in 0..7
    const float* xb = x + (size_t)b * T * CH;
    float s = 0.f;
    for (int t = r; t < T; t += 8) s += xb[t * CH + c];
    sm[c * 8 + r] = s;
    __syncthreads();
    if (tid < CH) {
        float tot = 0.f;
#pragma unroll
        for (int rr = 0; rr < 8; rr++) tot += sm[tid * 8 + rr];
        float m = tot * (1.0f / (float)T);
        g_mean[b][tid] = m;
        mean_s[tid] = m;
    }
    __syncthreads();
    if (tid < 4) {
        float sigma = fmaxf(mean_s[38 + 3 * tid], 0.001f);
        float inv = 0.5f / (sigma * sigma);
        float w[9];
        float sum = 0.f;
#pragma unroll
        for (int j = 0; j < 9; j++) {
            float k = (float)(j - 4);
            w[j] = expf(-k * k * inv);
            sum += w[j];
        }
        float rs = 1.0f / sum;
#pragma unroll
        for (int j = 0; j < 9; j++) g_w[b][tid][j] = w[j] * rs;
    }
}

// ---------------- lats: (env - mean_env) @ latent_slice ---------------------
// grid.x = B * WTOT * NTCH, 128 threads. Each thread owns 4 l-columns (float4),
// latent slice [12][tid*4..+3] held in registers across the whole t-chunk.
__global__ __launch_bounds__(128) void lats_kernel(
    const float* __restrict__ x,
    const float* __restrict__ lt,
    float* __restrict__ out)
{
    __shared__ float lat_s[12][LDIM];
    __shared__ float env_s[TC][12];

    int tid = threadIdx.x;
    int bidx = blockIdx.x;
    int wgl = bidx % WTOT;
    int tc  = (bidx / WTOT) % NTCH;
    int b   = bidx / (WTOT * NTCH);
    int sec = wgl / 6;
    int wl  = wgl % 6;
    int t0  = tc * TC;

    // latent slice: lt[(sec*12+h)*18*512 + (sec*6+wl)*512 + l]
    const float* latbase = lt + (size_t)(sec * 12) * (WTOT * LDIM) + (size_t)(sec * 6 + wl) * LDIM;
    for (int i = tid; i < 12 * LDIM; i += 128) {
        int h = i >> 9, l = i & (LDIM - 1);
        lat_s[h][l] = latbase[(size_t)h * WTOT * LDIM + l];
    }
    // envelope minus per-batch mean
    for (int i = tid; i < TC * 12; i += 128) {
        int tl = i / 12, h = i - tl * 12;
        env_s[tl][h] = x[((size_t)(b * T + t0 + tl)) * CH + sec * 12 + h]
                       - g_mean[b][sec * 12 + h];
    }
    __syncthreads();

    float4 lat4[12];
#pragma unroll
    for (int h = 0; h < 12; h++)
        lat4[h] = *(const float4*)&lat_s[h][tid * 4];

    float* outbase = out + (((size_t)(b * T + t0) * WTOT + wgl) * LDIM) + tid * 4;
#pragma unroll 2
    for (int tl = 0; tl < TC; tl++) {
        float4 acc = make_float4(0.f, 0.f, 0.f, 0.f);
#pragma unroll
        for (int h = 0; h < 12; h++) {
            float e = env_s[tl][h];
            acc.x = fmaf(e, lat4[h].x, acc.x);
            acc.y = fmaf(e, lat4[h].y, acc.y);
            acc.z = fmaf(e, lat4[h].z, acc.z);
            acc.w = fmaf(e, lat4[h].w, acc.w);
        }
        *(float4*)(outbase + (size_t)tl * WTOT * LDIM) = acc;
    }
}

// ---------------- noise: n = mu + sig*eps, 9-tap reflect gaussian along t ---
__global__ void noise_kernel(
    const float* __restrict__ x,
    const float4* __restrict__ eps,
    float4* __restrict__ out,
    int ni, int p4shift, int total)
{
    int idx = blockIdx.x * blockDim.x + threadIdx.x;
    if (idx >= total) return;
    int pv = idx & ((1 << p4shift) - 1);
    int bt = idx >> p4shift;
    int t = bt & (T - 1);
    int b = bt >> 11;

    float w[9];
    const float* wp = g_w[b][ni];
#pragma unroll
    for (int j = 0; j < 9; j++) w[j] = wp[j];

    const float* xb = x + (size_t)b * T * CH + 36 + 3 * ni;
    const float4* eb = eps + ((size_t)(b * T) << p4shift);

    float accm = 0.f;
    float4 acc = make_float4(0.f, 0.f, 0.f, 0.f);
#pragma unroll
    for (int j = 0; j < 9; j++) {
        int tj = t - 4 + j;
        tj = (tj < 0) ? -tj : tj;
        tj = (tj > T - 1) ? (2 * T - 2 - tj) : tj;
        float mu = xb[(size_t)tj * CH];
        float sg = xb[(size_t)tj * CH + 1];
        float s = w[j] * sg;
        accm = fmaf(w[j], mu, accm);
        float4 e = eb[((size_t)tj << p4shift) + pv];
        acc.x = fmaf(s, e.x, acc.x);
        acc.y = fmaf(s, e.y, acc.y);
        acc.z = fmaf(s, e.z, acc.z);
        acc.w = fmaf(s, e.w, acc.w);
    }
    out[idx] = make_float4(acc.x + accm, acc.y + accm, acc.z + accm, acc.w + accm);
}

extern "C" void kernel_launch(void* const* d_in, const int* in_sizes, int n_in,
                              void* d_out, int out_size)
{
    const float* x  = (const float*)d_in[0];
    const float* lt = (const float*)d_in[1];
    const float* eps[4] = {
        (const float*)d_in[2], (const float*)d_in[3],
        (const float*)d_in[4], (const float*)d_in[5]
    };
    float* out = (float*)d_out;

    stats_kernel<<<B, 384>>>(x);
    lats_kernel<<<B * WTOT * NTCH, 128>>>(x, lt, out);

    // output offsets (floats)
    size_t off = (size_t)B * T * WTOT * LDIM;   // 150,994,944
    int p4shift[4] = {2, 4, 6, 8};              // P/4 = 4,16,64,256
    for (int i = 0; i < 4; i++) {
        int p4 = 1 << p4shift[i];
        int total = B * T * p4;                 // vectorized (float4) elements
        int blocks = (total + 255) / 256;
        noise_kernel<<<blocks, 256>>>(x, (const float4*)eps[i],
                                      (float4*)(out + off), i, p4shift[i], total);
        off += (size_t)total * 4;
    }
}

// round 7
// speedup vs baseline: 1.1072x; 1.1072x over previous
#include <cuda_runtime.h>
#include <math.h>

// Shapes: B=8, T=2048, S=3, H=12, W_SPLIT=6, L=512, N_NOISE=4, R=4
// x: [8,2048,48], latents_table: [36,18,512], eps_i: [8,2048,(2^(i+2))^2]
// out = concat(lats [8,2048,18,512], noise0..3)

#define B 8
#define T 2048
#define CH 48
#define LDIM 512
#define WTOT 18
#define TC 128            // t-chunk for lats kernel
#define NTCH (T / TC)     // 16

__device__ float g_mean[B][CH];
__device__ float g_w[B][4][9];

typedef unsigned long long u64;

__device__ __forceinline__ u64 pack_dup(float a) {
    u64 r;
    unsigned int ai = __float_as_uint(a);
    asm("mov.b64 %0, {%1, %2};" : "=l"(r) : "r"(ai), "r"(ai));
    return r;
}
__device__ __forceinline__ u64 pack2(float a, float b) {
    u64 r;
    unsigned int ai = __float_as_uint(a), bi = __float_as_uint(b);
    asm("mov.b64 %0, {%1, %2};" : "=l"(r) : "r"(ai), "r"(bi));
    return r;
}
__device__ __forceinline__ void unpack2(u64 v, float& a, float& b) {
    unsigned int ai, bi;
    asm("mov.b64 {%0, %1}, %2;" : "=r"(ai), "=r"(bi) : "l"(v));
    a = __uint_as_float(ai); b = __uint_as_float(bi);
}
// d = a*b + d (packed fp32x2)
__device__ __forceinline__ void fma2(u64& d, u64 a, u64 b) {
    asm("fma.rn.f32x2 %0, %1, %2, %0;" : "+l"(d) : "l"(a), "l"(b));
}

// ---------------- stats: per-batch channel means + gaussian weights ----------
__global__ void stats_kernel(const float* __restrict__ x) {
    __shared__ float sm[CH * 8];
    __shared__ float mean_s[CH];
    int b = blockIdx.x;
    int tid = threadIdx.x;             // 384 threads
    int c = tid % CH, r = tid / CH;    // r in 0..7
    const float* xb = x + (size_t)b * T * CH;
    float s = 0.f;
    for (int t = r; t < T; t += 8) s += xb[t * CH + c];
    sm[c * 8 + r] = s;
    __syncthreads();
    if (tid < CH) {
        float tot = 0.f;
#pragma unroll
        for (int rr = 0; rr < 8; rr++) tot += sm[tid * 8 + rr];
        float m = tot * (1.0f / (float)T);
        g_mean[b][tid] = m;
        mean_s[tid] = m;
    }
    __syncthreads();
    if (tid < 4) {
        float sigma = fmaxf(mean_s[38 + 3 * tid], 0.001f);
        float inv = 0.5f / (sigma * sigma);
        float w[9];
        float sum = 0.f;
#pragma unroll
        for (int j = 0; j < 9; j++) {
            float k = (float)(j - 4);
            w[j] = expf(-k * k * inv);
            sum += w[j];
        }
        float rs = 1.0f / sum;
#pragma unroll
        for (int j = 0; j < 9; j++) g_w[b][tid][j] = w[j] * rs;
    }
}

// ---------------- lats: (env - mean_env) @ latent_slice ---------------------
// grid.x = B * WTOT * NTCH, 128 threads. Each thread owns 4 l-columns held as
// two packed f32x2 registers per h; env broadcast as packed (e,e) in shared.
// Inner loop is 24 FFMA2 per t instead of 48 FFMA.
__global__ __launch_bounds__(128) void lats_kernel(
    const float* __restrict__ x,
    const float* __restrict__ lt,
    float* __restrict__ out)
{
    __shared__ u64 env_p[TC][12];      // packed (e,e)

    int tid = threadIdx.x;
    int bidx = blockIdx.x;
    int wgl = bidx % WTOT;
    int tc  = (bidx / WTOT) % NTCH;
    int b   = bidx / (WTOT * NTCH);
    int sec = wgl / 6;
    int wl  = wgl % 6;
    int t0  = tc * TC;

    // envelope minus per-batch mean, packed broadcast
    for (int i = tid; i < TC * 12; i += 128) {
        int tl = i / 12, h = i - tl * 12;
        float e = x[((size_t)(b * T + t0 + tl)) * CH + sec * 12 + h]
                  - g_mean[b][sec * 12 + h];
        env_p[tl][h] = pack_dup(e);
    }

    // latent slice direct from global (coalesced float4 per h across warp)
    const float* latbase = lt + (size_t)(sec * 12) * (WTOT * LDIM)
                              + (size_t)(sec * 6 + wl) * LDIM + tid * 4;
    u64 latA[12], latB[12];
#pragma unroll
    for (int h = 0; h < 12; h++) {
        float4 v = *(const float4*)(latbase + (size_t)h * WTOT * LDIM);
        latA[h] = pack2(v.x, v.y);
        latB[h] = pack2(v.z, v.w);
    }
    __syncthreads();

    float* outbase = out + (((size_t)(b * T + t0) * WTOT + wgl) * LDIM) + tid * 4;
#pragma unroll 4
    for (int tl = 0; tl < TC; tl++) {
        u64 accA = 0ull, accB = 0ull;
#pragma unroll
        for (int h = 0; h < 12; h++) {
            u64 e2 = env_p[tl][h];
            fma2(accA, e2, latA[h]);
            fma2(accB, e2, latB[h]);
        }
        float4 o;
        unpack2(accA, o.x, o.y);
        unpack2(accB, o.z, o.w);
        *(float4*)(outbase + (size_t)tl * WTOT * LDIM) = o;
    }
}

// ---------------- noise: sliding-window 9-tap reflect gaussian along t ------
// Each thread produces TW consecutive t outputs for one pv (float4 of the
// spatial dim). The 9-tap eps/mu/sig window lives in registers; one new tap
// load per output -> read amplification (TW+8)/TW instead of 9x.
__device__ __forceinline__ int refl(int t) {
    t = (t < 0) ? -t : t;
    return (t > T - 1) ? (2 * T - 2 - t) : t;
}

template<int NI, int P4S, int TW>
__global__ __launch_bounds__(256) void noise_kernel(
    const float* __restrict__ x,
    const float4* __restrict__ eps,
    float4* __restrict__ out)
{
    const int P4 = 1 << P4S;
    const int NTC = T / TW;
    int idx = blockIdx.x * blockDim.x + threadIdx.x;
    int pv  = idx & (P4 - 1);
    int rest = idx >> P4S;
    int tc = rest % NTC;
    int b  = rest / NTC;
    if (b >= B) return;
    int t0 = tc * TW;

    float w[9];
    const float* wp = g_w[b][NI];
#pragma unroll
    for (int j = 0; j < 9; j++) w[j] = wp[j];

    const float* xb = x + (size_t)b * T * CH + 36 + 3 * NI;
    const float4* eb = eps + ((size_t)(b * T) << P4S) + pv;

    float4 e4[9]; float mm[9], ss[9];
#pragma unroll
    for (int j = 0; j < 9; j++) {
        int tj = refl(t0 - 4 + j);
        e4[j] = eb[(size_t)tj << P4S];
        mm[j] = xb[(size_t)tj * CH];
        ss[j] = xb[(size_t)tj * CH + 1];
    }

    float4* ob = out + (((size_t)(b * T + t0)) << P4S) + pv;
#pragma unroll
    for (int tt = 0; tt < TW; tt++) {
        float accm = 0.f;
        float4 acc = make_float4(0.f, 0.f, 0.f, 0.f);
#pragma unroll
        for (int j = 0; j < 9; j++) {
            int s = (tt + j) % 9;          // compile-time after full unroll
            accm = fmaf(w[j], mm[s], accm);
            float sc = w[j] * ss[s];
            acc.x = fmaf(sc, e4[s].x, acc.x);
            acc.y = fmaf(sc, e4[s].y, acc.y);
            acc.z = fmaf(sc, e4[s].z, acc.z);
            acc.w = fmaf(sc, e4[s].w, acc.w);
        }
        ob[(size_t)tt << P4S] = make_float4(acc.x + accm, acc.y + accm,
                                            acc.z + accm, acc.w + accm);
        // replace oldest tap (t0+tt-4) with t0+tt+5
        int tn = refl(t0 + tt + 5);
        int r = tt % 9;
        e4[r] = eb[(size_t)tn << P4S];
        mm[r] = xb[(size_t)tn * CH];
        ss[r] = xb[(size_t)tn * CH + 1];
    }
}

extern "C" void kernel_launch(void* const* d_in, const int* in_sizes, int n_in,
                              void* d_out, int out_size)
{
    const float* x  = (const float*)d_in[0];
    const float* lt = (const float*)d_in[1];
    float* out = (float*)d_out;

    stats_kernel<<<B, 384>>>(x);
    lats_kernel<<<B * WTOT * NTCH, 128>>>(x, lt, out);

    size_t off = (size_t)B * T * WTOT * LDIM;   // lats floats

    // i=0: P=16  -> P4=4,   TW=4  -> 16384 threads
    noise_kernel<0, 2, 4><<<(B * (T/4) * 4) / 256, 256>>>(
        x, (const float4*)d_in[2], (float4*)(out + off));
    off += (size_t)B * T * 16;

    // i=1: P=64  -> P4=16,  TW=8  -> 32768 threads
    noise_kernel<1, 4, 8><<<(B * (T/8) * 16) / 256, 256>>>(
        x, (const float4*)d_in[3], (float4*)(out + off));
    off += (size_t)B * T * 64;

    // i=2: P=256 -> P4=64,  TW=16 -> 65536 threads
    noise_kernel<2, 6, 16><<<(B * (T/16) * 64) / 256, 256>>>(
        x, (const float4*)d_in[4], (float4*)(out + off));
    off += (size_t)B * T * 256;

    // i=3: P=1024 -> P4=256, TW=16 -> 262144 threads
    noise_kernel<3, 8, 16><<<(B * (T/16) * 256) / 256, 256>>>(
        x, (const float4*)d_in[5], (float4*)(out + off));
}

// round 8
// speedup vs baseline: 1.2813x; 1.1572x over previous
#include <cuda_runtime.h>
#include <math.h>

// Shapes: B=8, T=2048, S=3, H=12, W_SPLIT=6, L=512, N_NOISE=4, R=4
// x: [8,2048,48], latents_table: [36,18,512], eps_i: [8,2048,(2^(i+2))^2]
// out = concat(lats [8,2048,18,512], noise0..3)

#define B 8
#define T 2048
#define CH 48
#define LDIM 512
#define WTOT 18
#define TC 128
#define NTCH (T / TC)     // 16

// fused grid layout: period-22 interleave of lats (9/period) and noise (13/period)
#define LATS_BLOCKS 1152        // B * NTCH * 9 (w-pairs)
#define NOISE_BLOCKS 1664       // 1024 + 256 + 256 + 128
#define TOTAL_BLOCKS 2816       // 128 periods of 22

__device__ float g_mean[B][CH];
__device__ float g_w[B][4][9];

typedef unsigned long long u64;

__device__ __forceinline__ u64 pack_dup(float a) {
    u64 r;
    unsigned int ai = __float_as_uint(a);
    asm("mov.b64 %0, {%1, %2};" : "=l"(r) : "r"(ai), "r"(ai));
    return r;
}
__device__ __forceinline__ u64 pack2(float a, float b) {
    u64 r;
    unsigned int ai = __float_as_uint(a), bi = __float_as_uint(b);
    asm("mov.b64 %0, {%1, %2};" : "=l"(r) : "r"(ai), "r"(bi));
    return r;
}
__device__ __forceinline__ void unpack2(u64 v, float& a, float& b) {
    unsigned int ai, bi;
    asm("mov.b64 {%0, %1}, %2;" : "=r"(ai), "=r"(bi) : "l"(v));
    a = __uint_as_float(ai); b = __uint_as_float(bi);
}
__device__ __forceinline__ void fma2(u64& d, u64 a, u64 b) {
    asm("fma.rn.f32x2 %0, %1, %2, %0;" : "+l"(d) : "l"(a), "l"(b));
}

// ---------------- stats ------------------------------------------------------
__global__ void stats_kernel(const float* __restrict__ x) {
    __shared__ float sm[CH * 8];
    __shared__ float mean_s[CH];
    int b = blockIdx.x;
    int tid = threadIdx.x;             // 384 threads
    int c = tid % CH, r = tid / CH;
    const float* xb = x + (size_t)b * T * CH;
    float s = 0.f;
    for (int t = r; t < T; t += 8) s += xb[t * CH + c];
    sm[c * 8 + r] = s;
    __syncthreads();
    if (tid < CH) {
        float tot = 0.f;
#pragma unroll
        for (int rr = 0; rr < 8; rr++) tot += sm[tid * 8 + rr];
        float m = tot * (1.0f / (float)T);
        g_mean[b][tid] = m;
        mean_s[tid] = m;
    }
    __syncthreads();
    if (tid < 4) {
        float sigma = fmaxf(mean_s[38 + 3 * tid], 0.001f);
        float inv = 0.5f / (sigma * sigma);
        float w[9];
        float sum = 0.f;
#pragma unroll
        for (int j = 0; j < 9; j++) {
            float k = (float)(j - 4);
            w[j] = expf(-k * k * inv);
            sum += w[j];
        }
        float rs = 1.0f / sum;
#pragma unroll
        for (int j = 0; j < 9; j++) g_w[b][tid][j] = w[j] * rs;
    }
}

// ---------------- lats device path ------------------------------------------
// 256 threads = 2 halves of 128; each half handles one w; thread owns 4 l-cols
// as packed f32x2 pairs. w-pairs (2k,2k+1) never straddle sections (6 even).
__device__ __forceinline__ void lats_block(
    int lbid, int tid,
    const float* __restrict__ x,
    const float* __restrict__ lt,
    float* __restrict__ out,
    u64 (*env_p)[12])
{
    int wpair = lbid % 9;
    int tc    = (lbid / 9) % NTCH;
    int b     = lbid / (9 * NTCH);
    int half  = tid >> 7;           // 0 or 1
    int t128  = tid & 127;
    int wgl   = wpair * 2 + half;
    int sec   = wgl / 6;
    int wl    = wgl % 6;
    int t0    = tc * TC;

    // env (same for both halves): TC*12 packed broadcasts
    for (int i = tid; i < TC * 12; i += 256) {
        int tl = i / 12, h = i - tl * 12;
        float e = x[((size_t)(b * T + t0 + tl)) * CH + sec * 12 + h]
                  - g_mean[b][sec * 12 + h];
        env_p[tl][h] = pack_dup(e);
    }

    const float* latbase = lt + (size_t)(sec * 12) * (WTOT * LDIM)
                              + (size_t)(sec * 6 + wl) * LDIM + t128 * 4;
    u64 latA[12], latB[12];
#pragma unroll
    for (int h = 0; h < 12; h++) {
        float4 v = *(const float4*)(latbase + (size_t)h * WTOT * LDIM);
        latA[h] = pack2(v.x, v.y);
        latB[h] = pack2(v.z, v.w);
    }
    __syncthreads();

    float* outbase = out + (((size_t)(b * T + t0) * WTOT + wgl) * LDIM) + t128 * 4;
#pragma unroll 4
    for (int tl = 0; tl < TC; tl++) {
        u64 accA = 0ull, accB = 0ull;
#pragma unroll
        for (int h = 0; h < 12; h++) {
            u64 e2 = env_p[tl][h];
            fma2(accA, e2, latA[h]);
            fma2(accB, e2, latB[h]);
        }
        float4 o;
        unpack2(accA, o.x, o.y);
        unpack2(accB, o.z, o.w);
        *(float4*)(outbase + (size_t)tl * WTOT * LDIM) = o;
    }
}

// ---------------- noise device path -----------------------------------------
__device__ __forceinline__ int refl(int t) {
    t = (t < 0) ? -t : t;
    return (t > T - 1) ? (2 * T - 2 - t) : t;
}

template<int NI, int P4S, int TW>
__device__ __forceinline__ void noise_block(
    int idx,                       // global thread index within this noise op
    const float* __restrict__ x,
    const float4* __restrict__ eps,
    float4* __restrict__ out)
{
    const int P4 = 1 << P4S;
    const int NTC = T / TW;
    int pv   = idx & (P4 - 1);
    int rest = idx >> P4S;
    int tc = rest % NTC;
    int b  = rest / NTC;
    if (b >= B) return;
    int t0 = tc * TW;

    float w[9];
    const float* wp = g_w[b][NI];
#pragma unroll
    for (int j = 0; j < 9; j++) w[j] = wp[j];

    const float* xb = x + (size_t)b * T * CH + 36 + 3 * NI;
    const float4* eb = eps + ((size_t)(b * T) << P4S) + pv;

    float4 e4[9]; float mm[9], ss[9];
#pragma unroll
    for (int j = 0; j < 9; j++) {
        int tj = refl(t0 - 4 + j);
        e4[j] = eb[(size_t)tj << P4S];
        mm[j] = xb[(size_t)tj * CH];
        ss[j] = xb[(size_t)tj * CH + 1];
    }

    float4* ob = out + (((size_t)(b * T + t0)) << P4S) + pv;
#pragma unroll
    for (int tt = 0; tt < TW; tt++) {
        float accm = 0.f;
        float4 acc = make_float4(0.f, 0.f, 0.f, 0.f);
#pragma unroll
        for (int j = 0; j < 9; j++) {
            int s = (tt + j) % 9;          // compile-time after unroll
            accm = fmaf(w[j], mm[s], accm);
            float sc = w[j] * ss[s];
            acc.x = fmaf(sc, e4[s].x, acc.x);
            acc.y = fmaf(sc, e4[s].y, acc.y);
            acc.z = fmaf(sc, e4[s].z, acc.z);
            acc.w = fmaf(sc, e4[s].w, acc.w);
        }
        ob[(size_t)tt << P4S] = make_float4(acc.x + accm, acc.y + accm,
                                            acc.z + accm, acc.w + accm);
        int tn = refl(t0 + tt + 5);
        int r = tt % 9;
        e4[r] = eb[(size_t)tn << P4S];
        mm[r] = xb[(size_t)tn * CH];
        ss[r] = xb[(size_t)tn * CH + 1];
    }
}

// ---------------- fused mega-kernel -----------------------------------------
// Per 22-block period: slots 0-8 -> lats, slots 9-21 -> noise.
// Noise global index order: [0,1024) n3, [1024,1280) n2, [1280,1536) n1,
// [1536,1664) n0.
__global__ __launch_bounds__(256) void fused_kernel(
    const float* __restrict__ x,
    const float* __restrict__ lt,
    const float4* __restrict__ e0, const float4* __restrict__ e1,
    const float4* __restrict__ e2, const float4* __restrict__ e3,
    float* __restrict__ out)
{
    __shared__ u64 env_p[TC][12];
    int bid = blockIdx.x;
    int p = bid / 22, s = bid - p * 22;
    int tid = threadIdx.x;

    if (s < 9) {
        lats_block(p * 9 + s, tid, x, lt, out, env_p);
        return;
    }
    int nb = p * 13 + (s - 9);      // 0..1663
    const size_t lats_f = (size_t)B * T * WTOT * LDIM;
    if (nb < 1024) {                 // noise3: P4=256, TW=16
        int idx = nb * 256 + tid;
        size_t off = lats_f + (size_t)B * T * (16 + 64 + 256);
        noise_block<3, 8, 16>(idx, x, e3, (float4*)(out + off));
    } else if (nb < 1280) {          // noise2: P4=64, TW=16
        int idx = (nb - 1024) * 256 + tid;
        size_t off = lats_f + (size_t)B * T * (16 + 64);
        noise_block<2, 6, 16>(idx, x, e2, (float4*)(out + off));
    } else if (nb < 1536) {          // noise1: P4=16, TW=4
        int idx = (nb - 1280) * 256 + tid;
        size_t off = lats_f + (size_t)B * T * 16;
        noise_block<1, 4, 4>(idx, x, e1, (float4*)(out + off));
    } else {                         // noise0: P4=4, TW=2
        int idx = (nb - 1536) * 256 + tid;
        noise_block<0, 2, 2>(idx, x, e0, (float4*)(out + lats_f));
    }
}

extern "C" void kernel_launch(void* const* d_in, const int* in_sizes, int n_in,
                              void* d_out, int out_size)
{
    const float* x  = (const float*)d_in[0];
    const float* lt = (const float*)d_in[1];
    float* out = (float*)d_out;

    stats_kernel<<<B, 384>>>(x);
    fused_kernel<<<TOTAL_BLOCKS, 256>>>(
        x, lt,
        (const float4*)d_in[2], (const float4*)d_in[3],
        (const float4*)d_in[4], (const float4*)d_in[5],
        out);
}